// round 8
// baseline (speedup 1.0000x reference)
#include <cuda_runtime.h>
#include <stdint.h>

#define NB 256
#define LL 1024
#define TT 128
#define THREADS 128
#define TSTRIDE 129
#define FULL 0xffffffffu

// smem layout (bytes) -- every section 16B-aligned
#define OFF_TRANST 0                               // 128*129*4 = 66048
#define OFF_BP     66048                           // 1024*128 = 131072 -> 197120
#define OFF_TAGS   197120                          // 4096 -> 201216
#define OFF_KCNT   201216                          // 2*4 ints = 32 -> 201248
#define OFF_SURV   201248                          // 2*128*8 = 2048 -> 203296
#define OFF_RED    203296                          // 1024 -> 204320
#define SMEM_BYTES 204320

__device__ int d_sched[NB];

// order-preserving float <-> uint map
__device__ __forceinline__ unsigned fmap(float f) {
    unsigned u = __float_as_uint(f);
    return (u & 0x80000000u) ? ~u : (u | 0x80000000u);
}
__device__ __forceinline__ float funmap(unsigned u) {
    return __uint_as_float((u & 0x80000000u) ? (u ^ 0x80000000u) : ~u);
}

__device__ __forceinline__ void upd(float &bv, int &bi, float sc, int i) {
    // first-argmax: strictly better, or equal with smaller index (order-independent)
    bool better = (sc > bv) || ((sc == bv) && (i < bi));
    bv = better ? sc : bv;
    bi = better ? i : bi;
}

// ---- pre-kernel: LPT schedule (bitonic sort, descending by length) ----
__global__ void sched_kernel(const int* __restrict__ lengths)
{
    __shared__ unsigned key[NB];
    int i = threadIdx.x;
    unsigned l = (unsigned)max(0, min(LL, lengths[i]));
    key[i] = (l << 8) | (255u - (unsigned)i);      // desc len, asc idx on ties
    __syncthreads();
    for (int k = 2; k <= NB; k <<= 1) {
        for (int j = k >> 1; j > 0; j >>= 1) {
            int ixj = i ^ j;
            if (ixj > i) {
                unsigned a = key[i], b2 = key[ixj];
                bool up = ((i & k) == 0);
                bool sw = up ? (a < b2) : (a > b2);
                if (sw) { key[i] = b2; key[ixj] = a; }
            }
            __syncthreads();
        }
    }
    d_sched[i] = 255 - (int)(key[i] & 0xFFu);
}

__global__ __launch_bounds__(THREADS, 1)
void crf_decode_kernel(const float* __restrict__ x,
                       const int* __restrict__ lengths,
                       const float* __restrict__ trans,
                       float* __restrict__ out)
{
    extern __shared__ char smem[];
    float*    s_transT = (float*)(smem + OFF_TRANST);   // [j][i] stride 129, conflict-free
    uint8_t*  s_bp     = (uint8_t*)(smem + OFF_BP);
    int*      s_tags   = (int*)(smem + OFF_TAGS);
    int*      s_kcnt   = (int*)(smem + OFF_KCNT);       // [2][4] per-warp survivor counts
    int2*     s_surv   = (int2*)(smem + OFF_SURV);      // [2][4][32] (valbits, idx)
    float*    s_red    = (float*)(smem + OFF_RED);      // mx[128], mn[128] / final state

    const int tid  = threadIdx.x;
    const int lane = tid & 31;
    const int w    = tid >> 5;
    const int b    = d_sched[blockIdx.x];

    int len = lengths[b];
    if (len > LL) len = LL;
    if (len < 1)  len = 1;

    // ---- transposed trans load + min/max fold ----
    {
        float mx = -3.4e38f, mn = 3.4e38f;
        #pragma unroll 4
        for (int i = 0; i < TT; ++i) {
            float v = trans[i * TT + tid];              // coalesced
            s_transT[tid * TSTRIDE + i] = v;            // conflict-free store
            mx = fmaxf(mx, v);
            mn = fminf(mn, v);
        }
        s_red[tid]       = mx;
        s_red[128 + tid] = mn;
    }
    __syncthreads();

    // every thread folds staged min/max identically -> identical D
    float D;
    {
        float gmx = -3.4e38f, gmn = 3.4e38f;
        const float4* r4 = (const float4*)s_red;        // 16B-aligned broadcast reads
        #pragma unroll 8
        for (int k = 0; k < 32; ++k) {
            float4 a = r4[k];
            gmx = fmaxf(gmx, fmaxf(fmaxf(a.x, a.y), fmaxf(a.z, a.w)));
            float4 c = r4[32 + k];
            gmn = fminf(gmn, fminf(fminf(c.x, c.y), fminf(c.z, c.w)));
        }
        D = (gmx - gmn) * 1.001f + 0.01f;               // exact-pruning width + fp margin
        if (!(D >= 0.01f && D <= 1000.0f)) D = 3.0e38f; // dense fallback if anomalous
    }

    const float* xb = x + (size_t)b * (LL * TT);
    float sj = xb[tid];                                 // state_0[j]

    // depth-3 x prefetch (guarded)
    float xA = (len > 1) ? xb[(size_t)1 * TT + tid] : 0.0f;
    float xB = (len > 2) ? xb[(size_t)2 * TT + tid] : 0.0f;
    float xC = (len > 3) ? xb[(size_t)3 * TT + tid] : 0.0f;

    const float* rowT = s_transT + tid * TSTRIDE;

    // publish survivors of state_0 into buffer 0 (per-warp threshold => superset, exact)
    int pq = 0;
    {
        float wmf = funmap(__reduce_max_sync(FULL, fmap(sj)));
        bool pred = (sj >= wmf - D);
        unsigned bal = __ballot_sync(FULL, pred);
        if (bal == 0u) { bal = FULL; pred = true; }     // unreachable with sane D
        int pos = __popc(bal & ((1u << lane) - 1u));
        if (pred) s_surv[(w << 5) + pos] = make_int2(__float_as_int(sj), tid);
        if (lane == 0) s_kcnt[w] = __popc(bal);
    }

    for (int t = 1; t < len; ++t) {
        __syncthreads();                                // single barrier per step

        // counts of the 4 per-warp survivor lists (one LDS.128)
        int4 kc = *(const int4*)(s_kcnt + (pq << 2));

        float xcur = xA; xA = xB; xB = xC;
        xC = (t + 3 < len) ? xb[(size_t)(t + 3) * TT + tid] : 0.0f;

        float best = -3.4e38f;
        int   bi   = 0;
        const int2* sb = s_surv + (pq << 7);
        #define SCAN(CNT, W2)                                              \
        { const int2* e2 = sb + ((W2) << 5);                               \
          for (int k = 0; k < (CNT); ++k) {                                \
              int2 e = e2[k];                                              \
              float v = __int_as_float(e.x) + rowT[e.y];                   \
              upd(best, bi, v, e.y);                                       \
          } }
        SCAN(kc.x, 0)
        SCAN(kc.y, 1)
        SCAN(kc.z, 2)
        SCAN(kc.w, 3)
        #undef SCAN

        s_bp[(t << 7) + tid] = (uint8_t)bi;
        sj = best + xcur;                               // reference op order

        // publish survivors of new state into the other buffer (race-free: disjoint)
        int np = pq ^ 1;
        float wmf = funmap(__reduce_max_sync(FULL, fmap(sj)));
        bool pred = (sj >= wmf - D);
        unsigned bal = __ballot_sync(FULL, pred);
        if (bal == 0u) { bal = FULL; pred = true; }
        int pos = __popc(bal & ((1u << lane) - 1u));
        if (pred) s_surv[(np << 7) + (w << 5) + pos] = make_int2(__float_as_int(sj), tid);
        if (lane == 0) s_kcnt[(np << 2) + w] = __popc(bal);

        pq = np;
    }

    // ---- final argmax (first-max) + backward walk ----
    s_red[tid] = sj;
    __syncthreads();
    if (tid == 0) {
        float bestf = s_red[0];
        int cand = 0;
        for (int i = 1; i < TT; ++i) {
            float v = s_red[i];
            if (v > bestf) { bestf = v; cand = i; }
        }
        int carry = cand;
        for (int t = len - 1; t >= 1; --t) {
            s_tags[t] = carry;
            carry = (int)s_bp[(t << 7) + carry];
        }
        s_tags[0] = carry;
    }
    __syncthreads();

    // ---- output: float32 tags for t < len, zeros beyond ----
    float* orow = out + b * LL;
    #pragma unroll 2
    for (int k = tid; k < LL / 4; k += THREADS) {
        int base = k << 2;
        float4 v;
        v.x = (base + 0 < len) ? (float)s_tags[base + 0] : 0.0f;
        v.y = (base + 1 < len) ? (float)s_tags[base + 1] : 0.0f;
        v.z = (base + 2 < len) ? (float)s_tags[base + 2] : 0.0f;
        v.w = (base + 3 < len) ? (float)s_tags[base + 3] : 0.0f;
        ((float4*)orow)[k] = v;
    }
}

extern "C" void kernel_launch(void* const* d_in, const int* in_sizes, int n_in,
                              void* d_out, int out_size)
{
    const float* x       = nullptr;
    const int*   lengths = nullptr;
    const float* trans   = nullptr;
    for (int i = 0; i < n_in; ++i) {
        long s = in_sizes[i];
        if      (s == 33554432L || s == 134217728L) x       = (const float*)d_in[i];
        else if (s == 256L      || s == 1024L)      lengths = (const int*)d_in[i];
        else if (s == 16384L    || s == 65536L)     trans   = (const float*)d_in[i];
    }
    if (!x       && n_in > 0) x       = (const float*)d_in[0];
    if (!lengths && n_in > 1) lengths = (const int*)d_in[1];
    if (!trans   && n_in > 3) trans   = (const float*)d_in[3];

    sched_kernel<<<1, NB>>>(lengths);

    cudaFuncSetAttribute(crf_decode_kernel,
                         cudaFuncAttributeMaxDynamicSharedMemorySize, SMEM_BYTES);
    crf_decode_kernel<<<NB, THREADS, SMEM_BYTES>>>(x, lengths, trans, (float*)d_out);
}

// round 10
// speedup vs baseline: 1.1559x; 1.1559x over previous
#include <cuda_runtime.h>
#include <stdint.h>

#define NB 256
#define LL 1024
#define TT 128
#define THREADS 128
#define TSTRIDE 129
#define FULL 0xffffffffu

// smem layout (bytes) -- every section 16B-aligned
#define OFF_TRANST 0                               // 128*129*4 = 66048
#define OFF_BP     66048                           // 131072 -> 197120
#define OFF_TAGS   197120                          // 4096  -> 201216
#define OFF_STATE  201216                          // 2*128*4 = 1024 -> 202240
#define OFF_WMAX   202240                          // 2*4*4 = 32 -> 202272
#define OFF_MASK   202272                          // 2*4*4 = 32 -> 202304
#define OFF_RED    202304                          // 1024 -> 203328
#define SMEM_BYTES 203328

__device__ int d_sched[NB];

// order-preserving float <-> uint map
__device__ __forceinline__ unsigned fmap(float f) {
    unsigned u = __float_as_uint(f);
    return (u & 0x80000000u) ? ~u : (u | 0x80000000u);
}
__device__ __forceinline__ float funmap(unsigned u) {
    return __uint_as_float((u & 0x80000000u) ? (u ^ 0x80000000u) : ~u);
}

__device__ __forceinline__ void upd(float &bv, int &bi, float sc, int i) {
    // first-argmax: strictly better, or equal with smaller index (order-independent)
    bool better = (sc > bv) || ((sc == bv) && (i < bi));
    bv = better ? sc : bv;
    bi = better ? i : bi;
}

// ---- pre-kernel: LPT schedule (bitonic sort, descending by length) ----
__global__ void sched_kernel(const int* __restrict__ lengths)
{
    __shared__ unsigned key[NB];
    int i = threadIdx.x;
    unsigned l = (unsigned)max(0, min(LL, lengths[i]));
    key[i] = (l << 8) | (255u - (unsigned)i);      // desc len, asc idx on ties
    __syncthreads();
    for (int k = 2; k <= NB; k <<= 1) {
        for (int j = k >> 1; j > 0; j >>= 1) {
            int ixj = i ^ j;
            if (ixj > i) {
                unsigned a = key[i], b2 = key[ixj];
                bool up = ((i & k) == 0);
                bool sw = up ? (a < b2) : (a > b2);
                if (sw) { key[i] = b2; key[ixj] = a; }
            }
            __syncthreads();
        }
    }
    d_sched[i] = 255 - (int)(key[i] & 0xFFu);
}

__global__ __launch_bounds__(THREADS, 1)
void crf_decode_kernel(const float* __restrict__ x,
                       const int* __restrict__ lengths,
                       const float* __restrict__ trans,
                       float* __restrict__ out)
{
    extern __shared__ char smem[];
    float*    s_transT = (float*)(smem + OFF_TRANST);   // [j][i] stride 129, conflict-free
    uint8_t*  s_bp     = (uint8_t*)(smem + OFF_BP);
    int*      s_tags   = (int*)(smem + OFF_TAGS);
    float*    s_state  = (float*)(smem + OFF_STATE);    // [2][128] double-buffered
    unsigned* s_wmax   = (unsigned*)(smem + OFF_WMAX);  // [2][4]
    unsigned* s_mask   = (unsigned*)(smem + OFF_MASK);  // [2][4]
    float*    s_red    = (float*)(smem + OFF_RED);      // staging / final state

    const int tid  = threadIdx.x;
    const int lane = tid & 31;
    const int w    = tid >> 5;
    const int b    = d_sched[blockIdx.x];

    int len = lengths[b];
    if (len > LL) len = LL;
    if (len < 1)  len = 1;

    // ---- transposed trans load + min/max fold ----
    {
        float mx = -3.4e38f, mn = 3.4e38f;
        #pragma unroll 4
        for (int i = 0; i < TT; ++i) {
            float v = trans[i * TT + tid];              // coalesced
            s_transT[tid * TSTRIDE + i] = v;            // conflict-free store
            mx = fmaxf(mx, v);
            mn = fminf(mn, v);
        }
        s_red[tid]       = mx;
        s_red[128 + tid] = mn;
    }
    __syncthreads();

    // all threads fold staged min/max identically -> identical D
    float D;
    {
        float gmx = -3.4e38f, gmn = 3.4e38f;
        const float4* r4 = (const float4*)s_red;        // 16B-aligned broadcast reads
        #pragma unroll 8
        for (int k = 0; k < 32; ++k) {
            float4 a = r4[k];
            gmx = fmaxf(gmx, fmaxf(fmaxf(a.x, a.y), fmaxf(a.z, a.w)));
            float4 c = r4[32 + k];
            gmn = fminf(gmn, fminf(fminf(c.x, c.y), fminf(c.z, c.w)));
        }
        D = (gmx - gmn) * 1.001f + 0.01f;               // exact-pruning width + fp margin
        if (!(D >= 0.01f && D <= 1000.0f)) D = 3.0e38f; // dense fallback if anomalous
    }

    const float* xb = x + (size_t)b * (LL * TT);
    float sj = xb[tid];                                 // state_0[j]

    // depth-3 x prefetch (guarded)
    float xA = (len > 1) ? xb[(size_t)1 * TT + tid] : 0.0f;
    float xB = (len > 2) ? xb[(size_t)2 * TT + tid] : 0.0f;
    float xC = (len > 3) ? xb[(size_t)3 * TT + tid] : 0.0f;

    const float* rowT = s_transT + tid * TSTRIDE;

    // publish state_0 + warp maxima into buffer 0
    s_state[tid] = sj;                                  // buffer 0
    {
        unsigned wm = __reduce_max_sync(FULL, fmap(sj));
        if (lane == 0) s_wmax[w] = wm;
    }
    __syncthreads();                                    // BAR1 of t=1

    for (int t = 1; t < len; ++t) {
        const int p  = (t - 1) & 1;                     // buffer holding state_{t-1}
        const int np = t & 1;

        // ---- phase 1: global threshold + ballot publish ----
        const unsigned* wmp = s_wmax + (p << 2);
        unsigned um = max(max(wmp[0], wmp[1]), max(wmp[2], wmp[3]));
        float thr = funmap(um) - D;
        unsigned bal = __ballot_sync(FULL, sj >= thr);
        if (lane == 0) s_mask[(p << 2) + w] = bal;
        __syncthreads();                                // BAR2

        // ---- phase 2: survivor scan + state update ----
        const uint4 mk = *(const uint4*)(s_mask + (p << 2));
        unsigned m0 = mk.x, m1 = mk.y, m2 = mk.z, m3 = mk.w;
        if ((m0 | m1 | m2 | m3) == 0u)                  // unreachable with sane D
            m0 = m1 = m2 = m3 = 0xffffffffu;

        float xcur = xA; xA = xB; xB = xC;
        xC = (t + 3 < len) ? xb[(size_t)(t + 3) * TT + tid] : 0.0f;

        const float* stp = s_state + (p << 7);
        float best = -3.4e38f;
        int   bi   = 0;
        #define SCAN(MASK, W2)                                             \
        { unsigned mm = (MASK);                                            \
          while (mm) {                                                     \
              int l2 = __ffs(mm) - 1; mm &= mm - 1;                        \
              int i  = ((W2) << 5) + l2;                                   \
              float v = stp[i] + rowT[i];                                  \
              upd(best, bi, v, i);                                         \
          } }
        SCAN(m0, 0)
        SCAN(m1, 1)
        SCAN(m2, 2)
        SCAN(m3, 3)
        #undef SCAN

        s_bp[(t << 7) + tid] = (uint8_t)bi;
        sj = best + xcur;                               // reference op order

        s_state[(np << 7) + tid] = sj;                  // write other buffer (race-free)
        unsigned wm = __reduce_max_sync(FULL, fmap(sj));
        if (lane == 0) s_wmax[(np << 2) + w] = wm;
        __syncthreads();                                // BAR1 of next step
    }

    // ---- final argmax (first-max) + backward walk ----
    s_red[tid] = sj;
    __syncthreads();
    if (tid == 0) {
        float bestf = s_red[0];
        int cand = 0;
        for (int i = 1; i < TT; ++i) {
            float v = s_red[i];
            if (v > bestf) { bestf = v; cand = i; }
        }
        int carry = cand;
        for (int t = len - 1; t >= 1; --t) {
            s_tags[t] = carry;
            carry = (int)s_bp[(t << 7) + carry];
        }
        s_tags[0] = carry;
    }
    __syncthreads();

    // ---- output: float32 tags for t < len, zeros beyond ----
    float* orow = out + b * LL;
    #pragma unroll 2
    for (int k = tid; k < LL / 4; k += THREADS) {
        int base = k << 2;
        float4 v;
        v.x = (base + 0 < len) ? (float)s_tags[base + 0] : 0.0f;
        v.y = (base + 1 < len) ? (float)s_tags[base + 1] : 0.0f;
        v.z = (base + 2 < len) ? (float)s_tags[base + 2] : 0.0f;
        v.w = (base + 3 < len) ? (float)s_tags[base + 3] : 0.0f;
        ((float4*)orow)[k] = v;
    }
}

extern "C" void kernel_launch(void* const* d_in, const int* in_sizes, int n_in,
                              void* d_out, int out_size)
{
    const float* x       = nullptr;
    const int*   lengths = nullptr;
    const float* trans   = nullptr;
    for (int i = 0; i < n_in; ++i) {
        long s = in_sizes[i];
        if      (s == 33554432L || s == 134217728L) x       = (const float*)d_in[i];
        else if (s == 256L      || s == 1024L)      lengths = (const int*)d_in[i];
        else if (s == 16384L    || s == 65536L)     trans   = (const float*)d_in[i];
    }
    if (!x       && n_in > 0) x       = (const float*)d_in[0];
    if (!lengths && n_in > 1) lengths = (const int*)d_in[1];
    if (!trans   && n_in > 3) trans   = (const float*)d_in[3];

    sched_kernel<<<1, NB>>>(lengths);

    cudaFuncSetAttribute(crf_decode_kernel,
                         cudaFuncAttributeMaxDynamicSharedMemorySize, SMEM_BYTES);
    crf_decode_kernel<<<NB, THREADS, SMEM_BYTES>>>(x, lengths, trans, (float*)d_out);
}